// round 1
// baseline (speedup 1.0000x reference)
#include <cuda_runtime.h>
#include <cstdint>

#define HD    1024
#define BATCH 1024
#define SEQL  128
#define G4    4096
#define NCLS  10

#define BM 128
#define BN 256
#define BK 32
#define LDA 36                 // BK + 4 pad (keeps 16B align: 36 floats = 144B = 9*16)
#define KT_ITERS (HD / BK)     // 32

// ---- persistent device scratch (allocation-free) ----
__device__ float g_Wpack[(size_t)G4 * HD];   // packed recurrent weights [4096][1024]
__device__ float g_wxp[G4];                  // packed x-weights (IN_DIM==1)
__device__ float g_bp[G4];                   // packed biases
__device__ float g_h[2][(size_t)BATCH * HD]; // ping-pong hidden state
__device__ float g_c[(size_t)BATCH * HD];    // cell state

// Packed column layout: for s = j/4, q = j%4:
//   col 16s + 2q + 0 = g_j     col 16s + 2q + 1 = i_j
//   col 16s + 8 + 2q + 0 = f_j col 16s + 8 + 2q + 1 = o_j
// This makes each mma thread (lane%4 = q) own (g_j,i_j) in even 8-col n-tiles
// and (f_j,o_j) of the SAME j in the following odd n-tile -> register-local gates.
__global__ void pack_kernel(const float* __restrict__ wgh, const float* __restrict__ wih,
                            const float* __restrict__ wfh, const float* __restrict__ woh,
                            const float* __restrict__ wgx, const float* __restrict__ wix,
                            const float* __restrict__ wfx, const float* __restrict__ wox,
                            const float* __restrict__ bg, const float* __restrict__ bi,
                            const float* __restrict__ bf, const float* __restrict__ bo) {
    int total = G4 * HD;
    for (int idx = blockIdx.x * blockDim.x + threadIdx.x; idx < total;
         idx += gridDim.x * blockDim.x) {
        int p = idx >> 10;          // packed col
        int k = idx & (HD - 1);
        int s = p >> 4, r = p & 15;
        int q    = (r < 8) ? (r >> 1) : ((r - 8) >> 1);
        int gate = (r < 8) ? (r & 1) : (2 + (r & 1));
        int j = (s << 2) + q;
        const float* w = (gate == 0) ? wgh : (gate == 1) ? wih : (gate == 2) ? wfh : woh;
        g_Wpack[(size_t)p * HD + k] = w[(size_t)j * HD + k];
        if (k == 0) {
            const float* wx = (gate == 0) ? wgx : (gate == 1) ? wix : (gate == 2) ? wfx : wox;
            const float* bb = (gate == 0) ? bg  : (gate == 1) ? bi  : (gate == 2) ? bf  : bo;
            g_wxp[p] = wx[j];
            g_bp[p]  = bb[j];
        }
    }
}

__global__ void init_kernel() {
    int n = BATCH * HD;
    for (int i = blockIdx.x * blockDim.x + threadIdx.x; i < n;
         i += gridDim.x * blockDim.x) {
        g_h[0][i] = 0.f;
        g_c[i]    = 0.f;
    }
}

__device__ __forceinline__ void cp16(float* s, const float* g) {
    uint32_t sa = (uint32_t)__cvta_generic_to_shared(s);
    asm volatile("cp.async.cg.shared.global [%0], [%1], 16;\n" :: "r"(sa), "l"(g) : "memory");
}

__device__ __forceinline__ void mma_tf32(float& d0, float& d1, float& d2, float& d3,
                                         uint32_t a0, uint32_t a1, uint32_t a2, uint32_t a3,
                                         uint32_t b0, uint32_t b1) {
    asm volatile(
        "mma.sync.aligned.m16n8k8.row.col.f32.tf32.tf32.f32 "
        "{%0,%1,%2,%3}, {%4,%5,%6,%7}, {%8,%9}, {%0,%1,%2,%3};\n"
        : "+f"(d0), "+f"(d1), "+f"(d2), "+f"(d3)
        : "r"(a0), "r"(a1), "r"(a2), "r"(a3), "r"(b0), "r"(b1));
}

__device__ __forceinline__ float sigmoidf_fast(float v) {
    return 1.f / (1.f + __expf(-v));
}

// One timestep: pre = h_in @ Wpack^T (+ x_t * wxp + bias), gates, update c, write h_out.
// Grid: (G4/BN, BATCH/BM) = (16, 8). 256 threads. Warp layout 2(m) x 4(n), warp tile 64x64.
__global__ __launch_bounds__(256, 1)
void step_kernel(const float* __restrict__ x, int t) {
    const float* __restrict__ h_in  = g_h[t & 1];
    float* __restrict__       h_out = g_h[(t + 1) & 1];

    extern __shared__ float smem[];
    float* As = smem;                  // [2][BM][LDA]
    float* Bs = smem + 2 * BM * LDA;   // [2][BN][LDA]

    int tid = threadIdx.x;
    int lane = tid & 31, wid = tid >> 5;
    int wm = wid & 1, wn = wid >> 1;
    int lr = lane >> 2, lc = lane & 3;

    int m0 = blockIdx.y * BM;
    int n0 = blockIdx.x * BN;

    float acc[4][8][4];
#pragma unroll
    for (int a = 0; a < 4; a++)
#pragma unroll
        for (int b = 0; b < 8; b++)
#pragma unroll
            for (int cI = 0; cI < 4; cI++) acc[a][b][cI] = 0.f;

    auto load_tiles = [&](int kt, int buf) {
        const float* hA = h_in    + (size_t)m0 * HD + kt * BK;
        const float* wB = g_Wpack + (size_t)n0 * HD + kt * BK;
        float* Ab = As + buf * BM * LDA;
        float* Bb = Bs + buf * BN * LDA;
#pragma unroll
        for (int i = 0; i < 4; i++) {           // A: 128 rows x 8 16B-chunks
            int cidx = tid + i * 256;
            int row = cidx >> 3, ch = (cidx & 7) << 2;
            cp16(Ab + row * LDA + ch, hA + (size_t)row * HD + ch);
        }
#pragma unroll
        for (int i = 0; i < 8; i++) {           // B: 256 rows x 8 16B-chunks
            int cidx = tid + i * 256;
            int row = cidx >> 3, ch = (cidx & 7) << 2;
            cp16(Bb + row * LDA + ch, wB + (size_t)row * HD + ch);
        }
        asm volatile("cp.async.commit_group;\n" ::: "memory");
    };

    load_tiles(0, 0);
    asm volatile("cp.async.wait_group 0;\n" ::: "memory");
    __syncthreads();

    for (int kt = 0; kt < KT_ITERS; kt++) {
        int buf = kt & 1;
        if (kt + 1 < KT_ITERS) load_tiles(kt + 1, buf ^ 1);

        const float* Ab = As + buf * BM * LDA + (wm * 64 + lr) * LDA;
        const float* Bb = Bs + buf * BN * LDA + (wn * 64 + lr) * LDA;
#pragma unroll
        for (int kk = 0; kk < 4; kk++) {
            int kb = kk * 8 + lc;
            uint32_t af[4][4];
            uint32_t bfr[8][2];
#pragma unroll
            for (int mi = 0; mi < 4; mi++) {
                const float* ap = Ab + mi * 16 * LDA;
                af[mi][0] = __float_as_uint(ap[kb]);
                af[mi][1] = __float_as_uint(ap[8 * LDA + kb]);
                af[mi][2] = __float_as_uint(ap[kb + 4]);
                af[mi][3] = __float_as_uint(ap[8 * LDA + kb + 4]);
            }
#pragma unroll
            for (int ni = 0; ni < 8; ni++) {
                const float* bp2 = Bb + ni * 8 * LDA;
                bfr[ni][0] = __float_as_uint(bp2[kb]);
                bfr[ni][1] = __float_as_uint(bp2[kb + 4]);
            }
#pragma unroll
            for (int mi = 0; mi < 4; mi++)
#pragma unroll
                for (int ni = 0; ni < 8; ni++)
                    mma_tf32(acc[mi][ni][0], acc[mi][ni][1], acc[mi][ni][2], acc[mi][ni][3],
                             af[mi][0], af[mi][1], af[mi][2], af[mi][3],
                             bfr[ni][0], bfr[ni][1]);
        }
        asm volatile("cp.async.wait_group 0;\n" ::: "memory");
        __syncthreads();
    }

    // ---- epilogue: gates + LSTM state update, fully register-local ----
    int nbase = n0 + wn * 64;
#pragma unroll
    for (int mi = 0; mi < 4; mi++) {
        int r0 = m0 + wm * 64 + mi * 16 + lr;
        int r1 = r0 + 8;
        float x0 = x[r0 * SEQL + t];
        float x1 = x[r1 * SEQL + t];
#pragma unroll
        for (int p = 0; p < 4; p++) {
            int cg = nbase + p * 16 + 2 * lc;   // g col (i at +1)
            int cf = cg + 8;                    // f col (o at +1)
            int j  = (nbase >> 2) + p * 4 + lc; // hidden index
            float wgv = g_wxp[cg],     wiv = g_wxp[cg + 1];
            float wfv = g_wxp[cf],     wov = g_wxp[cf + 1];
            float bgv = g_bp[cg],      biv = g_bp[cg + 1];
            float bfv = g_bp[cf],      bov = g_bp[cf + 1];
            int e = 2 * p, od = 2 * p + 1;
            {   // row r0
                float pg = acc[mi][e][0]  + x0 * wgv + bgv;
                float pi = acc[mi][e][1]  + x0 * wiv + biv;
                float pf = acc[mi][od][0] + x0 * wfv + bfv;
                float po = acc[mi][od][1] + x0 * wov + bov;
                float gv = tanhf(pg);
                float iv = sigmoidf_fast(pi);
                float fv = sigmoidf_fast(pf);
                float ov = sigmoidf_fast(po);
                size_t off = (size_t)r0 * HD + j;
                float cn = gv * iv + g_c[off] * fv;
                g_c[off] = cn;
                h_out[off] = tanhf(cn) * ov;
            }
            {   // row r1
                float pg = acc[mi][e][2]  + x1 * wgv + bgv;
                float pi = acc[mi][e][3]  + x1 * wiv + biv;
                float pf = acc[mi][od][2] + x1 * wfv + bfv;
                float po = acc[mi][od][3] + x1 * wov + bov;
                float gv = tanhf(pg);
                float iv = sigmoidf_fast(pi);
                float fv = sigmoidf_fast(pf);
                float ov = sigmoidf_fast(po);
                size_t off = (size_t)r1 * HD + j;
                float cn = gv * iv + g_c[off] * fv;
                g_c[off] = cn;
                h_out[off] = tanhf(cn) * ov;
            }
        }
    }
}

// logits[b,n] = h_last[b,:] . w_ph[n,:] + bias_p[n]; h_last = g_h[0] (after 128 steps)
__global__ void logits_kernel(const float* __restrict__ wph, const float* __restrict__ bp,
                              float* __restrict__ out) {
    int b = blockIdx.x;
    int lane = threadIdx.x;   // 32 threads
    const float* hrow = g_h[0] + (size_t)b * HD;
    float accv[NCLS];
#pragma unroll
    for (int n = 0; n < NCLS; n++) accv[n] = 0.f;
    for (int k = lane; k < HD; k += 32) {
        float hv = hrow[k];
#pragma unroll
        for (int n = 0; n < NCLS; n++) accv[n] += hv * wph[(size_t)n * HD + k];
    }
#pragma unroll
    for (int n = 0; n < NCLS; n++)
#pragma unroll
        for (int off = 16; off; off >>= 1)
            accv[n] += __shfl_xor_sync(0xffffffffu, accv[n], off);
    if (lane < NCLS) out[b * NCLS + lane] = accv[lane] + bp[lane];
}

extern "C" void kernel_launch(void* const* d_in, const int* in_sizes, int n_in,
                              void* d_out, int out_size) {
    const float* x   = (const float*)d_in[0];
    const float* wgx = (const float*)d_in[1];
    const float* wgh = (const float*)d_in[2];
    const float* wix = (const float*)d_in[3];
    const float* wih = (const float*)d_in[4];
    const float* wfx = (const float*)d_in[5];
    const float* wfh = (const float*)d_in[6];
    const float* wox = (const float*)d_in[7];
    const float* woh = (const float*)d_in[8];
    const float* wph = (const float*)d_in[9];
    const float* bg  = (const float*)d_in[10];
    const float* bi  = (const float*)d_in[11];
    const float* bf  = (const float*)d_in[12];
    const float* bo  = (const float*)d_in[13];
    const float* bp  = (const float*)d_in[14];
    float* out = (float*)d_out;

    const int SMEM_BYTES = 2 * (BM + BN) * LDA * (int)sizeof(float);  // 110592
    cudaFuncSetAttribute(step_kernel, cudaFuncAttributeMaxDynamicSharedMemorySize, SMEM_BYTES);

    pack_kernel<<<2048, 256>>>(wgh, wih, wfh, woh, wgx, wix, wfx, wox, bg, bi, bf, bo);
    init_kernel<<<2048, 256>>>();

    dim3 grid(G4 / BN, BATCH / BM);   // (16, 8) = 128 CTAs
    for (int t = 0; t < SEQL; t++)
        step_kernel<<<grid, 256, SMEM_BYTES>>>(x, t);

    logits_kernel<<<BATCH, 32>>>(wph, bp, out);
}

// round 4
// speedup vs baseline: 1.0424x; 1.0424x over previous
#include <cuda_runtime.h>
#include <cstdint>

#define HD    1024
#define BATCH 1024
#define SEQL  128
#define G4    4096
#define NCLS  10

#define BM 128
#define BN 256
#define BK 32
#define LDA 36                 // BK + 4 pad (16B-aligned rows: 36 floats = 144B)
#define KT_ITERS (HD / BK)     // 32
#define THREADS 512

// ---- persistent device scratch (allocation-free) ----
__device__ float g_Wpack[(size_t)G4 * HD];   // packed recurrent weights [4096][1024]
__device__ float g_wxp[G4];                  // packed x-weights (IN_DIM==1)
__device__ float g_bp[G4];                   // packed biases
__device__ float g_h[2][(size_t)BATCH * HD]; // ping-pong hidden state
__device__ float g_c[(size_t)BATCH * HD];    // cell state

// Packed column layout: for s = j/4, q = j%4:
//   col 16s + 2q + 0 = g_j     col 16s + 2q + 1 = i_j
//   col 16s + 8 + 2q + 0 = f_j col 16s + 8 + 2q + 1 = o_j
// Each mma thread (lane%4 = q) owns (g_j,i_j) in even 8-col n-tiles and
// (f_j,o_j) of the SAME j in the adjacent odd n-tile -> register-local gates.
__global__ void pack_kernel(const float* __restrict__ wgh, const float* __restrict__ wih,
                            const float* __restrict__ wfh, const float* __restrict__ woh,
                            const float* __restrict__ wgx, const float* __restrict__ wix,
                            const float* __restrict__ wfx, const float* __restrict__ wox,
                            const float* __restrict__ bg, const float* __restrict__ bi,
                            const float* __restrict__ bf, const float* __restrict__ bo) {
    int total = G4 * HD;
    for (int idx = blockIdx.x * blockDim.x + threadIdx.x; idx < total;
         idx += gridDim.x * blockDim.x) {
        int p = idx >> 10;          // packed col
        int k = idx & (HD - 1);
        int s = p >> 4, r = p & 15;
        int q    = (r < 8) ? (r >> 1) : ((r - 8) >> 1);
        int gate = (r < 8) ? (r & 1) : (2 + (r & 1));
        int j = (s << 2) + q;
        const float* w = (gate == 0) ? wgh : (gate == 1) ? wih : (gate == 2) ? wfh : woh;
        g_Wpack[(size_t)p * HD + k] = w[(size_t)j * HD + k];
        if (k == 0) {
            const float* wx = (gate == 0) ? wgx : (gate == 1) ? wix : (gate == 2) ? wfx : wox;
            const float* bb = (gate == 0) ? bg  : (gate == 1) ? bi  : (gate == 2) ? bf  : bo;
            g_wxp[p] = wx[j];
            g_bp[p]  = bb[j];
        }
    }
}

__global__ void init_kernel() {
    int n = BATCH * HD;
    for (int i = blockIdx.x * blockDim.x + threadIdx.x; i < n;
         i += gridDim.x * blockDim.x) {
        g_h[0][i] = 0.f;
        g_c[i]    = 0.f;
    }
}

__device__ __forceinline__ void cp16(float* s, const float* g) {
    uint32_t sa = (uint32_t)__cvta_generic_to_shared(s);
    asm volatile("cp.async.cg.shared.global [%0], [%1], 16;\n" :: "r"(sa), "l"(g) : "memory");
}

__device__ __forceinline__ void mma_tf32(float& d0, float& d1, float& d2, float& d3,
                                         uint32_t a0, uint32_t a1, uint32_t a2, uint32_t a3,
                                         uint32_t b0, uint32_t b1) {
    asm volatile(
        "mma.sync.aligned.m16n8k8.row.col.f32.tf32.tf32.f32 "
        "{%0,%1,%2,%3}, {%4,%5,%6,%7}, {%8,%9}, {%0,%1,%2,%3};\n"
        : "+f"(d0), "+f"(d1), "+f"(d2), "+f"(d3)
        : "r"(a0), "r"(a1), "r"(a2), "r"(a3), "r"(b0), "r"(b1));
}

__device__ __forceinline__ float sigmoidf_fast(float v) {
    return 1.f / (1.f + __expf(-v));
}

// One timestep: pre = h_in @ Wpack^T (+ x_t * wxp + bias), gates, update c, write h_out.
// Grid: (G4/BN, BATCH/BM) = (16, 8). 512 threads, 16 warps: 2(m) x 8(n), warp tile 64x32.
__global__ __launch_bounds__(THREADS, 1)
void step_kernel(const float* __restrict__ x, int t) {
    const float* __restrict__ h_in  = g_h[t & 1];
    float* __restrict__       h_out = g_h[(t + 1) & 1];

    extern __shared__ float smem[];
    float* As = smem;                  // [2][BM][LDA]
    float* Bs = smem + 2 * BM * LDA;   // [2][BN][LDA]

    int tid = threadIdx.x;
    int lane = tid & 31, wid = tid >> 5;
    int wm = wid & 1, wn = wid >> 1;   // 2 x 8 warp grid
    int lr = lane >> 2, lc = lane & 3;

    int m0 = blockIdx.y * BM;
    int n0 = blockIdx.x * BN;

    float acc[4][4][4];
#pragma unroll
    for (int a = 0; a < 4; a++)
#pragma unroll
        for (int b = 0; b < 4; b++)
#pragma unroll
            for (int cI = 0; cI < 4; cI++) acc[a][b][cI] = 0.f;

    auto load_tiles = [&](int kt, int buf) {
        const float* hA = h_in    + (size_t)m0 * HD + kt * BK;
        const float* wB = g_Wpack + (size_t)n0 * HD + kt * BK;
        float* Ab = As + buf * BM * LDA;
        float* Bb = Bs + buf * BN * LDA;
#pragma unroll
        for (int i = 0; i < 2; i++) {           // A: 128 rows x 8 16B-chunks = 1024
            int cidx = tid + i * THREADS;
            int row = cidx >> 3, ch = (cidx & 7) << 2;
            cp16(Ab + row * LDA + ch, hA + (size_t)row * HD + ch);
        }
#pragma unroll
        for (int i = 0; i < 4; i++) {           // B: 256 rows x 8 16B-chunks = 2048
            int cidx = tid + i * THREADS;
            int row = cidx >> 3, ch = (cidx & 7) << 2;
            cp16(Bb + row * LDA + ch, wB + (size_t)row * HD + ch);
        }
        asm volatile("cp.async.commit_group;\n" ::: "memory");
    };

    load_tiles(0, 0);
    asm volatile("cp.async.wait_group 0;\n" ::: "memory");
    __syncthreads();

    for (int kt = 0; kt < KT_ITERS; kt++) {
        int buf = kt & 1;
        if (kt + 1 < KT_ITERS) load_tiles(kt + 1, buf ^ 1);

        const float* Ab = As + buf * BM * LDA + (wm * 64 + lr) * LDA;
        const float* Bb = Bs + buf * BN * LDA + (wn * 32 + lr) * LDA;
#pragma unroll
        for (int kk = 0; kk < 4; kk++) {
            int kb = kk * 8 + lc;
            uint32_t af[4][4];
            uint32_t bfr[4][2];
#pragma unroll
            for (int mi = 0; mi < 4; mi++) {
                const float* ap = Ab + mi * 16 * LDA;
                af[mi][0] = __float_as_uint(ap[kb]);
                af[mi][1] = __float_as_uint(ap[8 * LDA + kb]);
                af[mi][2] = __float_as_uint(ap[kb + 4]);
                af[mi][3] = __float_as_uint(ap[8 * LDA + kb + 4]);
            }
#pragma unroll
            for (int ni = 0; ni < 4; ni++) {
                const float* bp2 = Bb + ni * 8 * LDA;
                bfr[ni][0] = __float_as_uint(bp2[kb]);
                bfr[ni][1] = __float_as_uint(bp2[kb + 4]);
            }
#pragma unroll
            for (int mi = 0; mi < 4; mi++)
#pragma unroll
                for (int ni = 0; ni < 4; ni++)
                    mma_tf32(acc[mi][ni][0], acc[mi][ni][1], acc[mi][ni][2], acc[mi][ni][3],
                             af[mi][0], af[mi][1], af[mi][2], af[mi][3],
                             bfr[ni][0], bfr[ni][1]);
        }
        asm volatile("cp.async.wait_group 0;\n" ::: "memory");
        __syncthreads();
    }

    // ---- epilogue: gates + LSTM state update, fully register-local ----
    int nbase = n0 + wn * 32;
#pragma unroll
    for (int mi = 0; mi < 4; mi++) {
        int r0 = m0 + wm * 64 + mi * 16 + lr;
        int r1 = r0 + 8;
        float x0 = x[r0 * SEQL + t];
        float x1 = x[r1 * SEQL + t];
#pragma unroll
        for (int p = 0; p < 2; p++) {
            int cg = nbase + p * 16 + 2 * lc;   // g col (i at +1)
            int cf = cg + 8;                    // f col (o at +1)
            int j  = (nbase >> 2) + p * 4 + lc; // hidden index
            float wgv = g_wxp[cg],     wiv = g_wxp[cg + 1];
            float wfv = g_wxp[cf],     wov = g_wxp[cf + 1];
            float bgv = g_bp[cg],      biv = g_bp[cg + 1];
            float bfv = g_bp[cf],      bov = g_bp[cf + 1];
            int e = 2 * p, od = 2 * p + 1;
            {   // row r0
                float pg = acc[mi][e][0]  + x0 * wgv + bgv;
                float pi = acc[mi][e][1]  + x0 * wiv + biv;
                float pf = acc[mi][od][0] + x0 * wfv + bfv;
                float po = acc[mi][od][1] + x0 * wov + bov;
                float gv = tanhf(pg);
                float iv = sigmoidf_fast(pi);
                float fv = sigmoidf_fast(pf);
                float ov = sigmoidf_fast(po);
                size_t off = (size_t)r0 * HD + j;
                float cn = gv * iv + g_c[off] * fv;
                g_c[off] = cn;
                h_out[off] = tanhf(cn) * ov;
            }
            {   // row r1
                float pg = acc[mi][e][2]  + x1 * wgv + bgv;
                float pi = acc[mi][e][3]  + x1 * wiv + biv;
                float pf = acc[mi][od][2] + x1 * wfv + bfv;
                float po = acc[mi][od][3] + x1 * wov + bov;
                float gv = tanhf(pg);
                float iv = sigmoidf_fast(pi);
                float fv = sigmoidf_fast(pf);
                float ov = sigmoidf_fast(po);
                size_t off = (size_t)r1 * HD + j;
                float cn = gv * iv + g_c[off] * fv;
                g_c[off] = cn;
                h_out[off] = tanhf(cn) * ov;
            }
        }
    }
}

// logits[b,n] = h_last[b,:] . w_ph[n,:] + bias_p[n]; h_last = g_h[0] (after 128 steps)
__global__ void logits_kernel(const float* __restrict__ wph, const float* __restrict__ bp,
                              float* __restrict__ out) {
    int b = blockIdx.x;
    int lane = threadIdx.x;   // 32 threads
    const float* hrow = g_h[0] + (size_t)b * HD;
    float accv[NCLS];
#pragma unroll
    for (int n = 0; n < NCLS; n++) accv[n] = 0.f;
    for (int k = lane; k < HD; k += 32) {
        float hv = hrow[k];
#pragma unroll
        for (int n = 0; n < NCLS; n++) accv[n] += hv * wph[(size_t)n * HD + k];
    }
#pragma unroll
    for (int n = 0; n < NCLS; n++)
#pragma unroll
        for (int off = 16; off; off >>= 1)
            accv[n] += __shfl_xor_sync(0xffffffffu, accv[n], off);
    if (lane < NCLS) out[b * NCLS + lane] = accv[lane] + bp[lane];
}

extern "C" void kernel_launch(void* const* d_in, const int* in_sizes, int n_in,
                              void* d_out, int out_size) {
    const float* x   = (const float*)d_in[0];
    const float* wgx = (const float*)d_in[1];
    const float* wgh = (const float*)d_in[2];
    const float* wix = (const float*)d_in[3];
    const float* wih = (const float*)d_in[4];
    const float* wfx = (const float*)d_in[5];
    const float* wfh = (const float*)d_in[6];
    const float* wox = (const float*)d_in[7];
    const float* woh = (const float*)d_in[8];
    const float* wph = (const float*)d_in[9];
    const float* bg  = (const float*)d_in[10];
    const float* bi  = (const float*)d_in[11];
    const float* bf  = (const float*)d_in[12];
    const float* bo  = (const float*)d_in[13];
    const float* bp  = (const float*)d_in[14];
    float* out = (float*)d_out;

    const int SMEM_BYTES = 2 * (BM + BN) * LDA * (int)sizeof(float);  // 110592
    cudaFuncSetAttribute(step_kernel, cudaFuncAttributeMaxDynamicSharedMemorySize, SMEM_BYTES);

    pack_kernel<<<2048, 256>>>(wgh, wih, wfh, woh, wgx, wix, wfx, wox, bg, bi, bf, bo);
    init_kernel<<<2048, 256>>>();

    dim3 grid(G4 / BN, BATCH / BM);   // (16, 8) = 128 CTAs
    for (int t = 0; t < SEQL; t++)
        step_kernel<<<grid, THREADS, SMEM_BYTES>>>(x, t);

    logits_kernel<<<BATCH, 32>>>(wph, bp, out);
}